// round 9
// baseline (speedup 1.0000x reference)
#include <cuda_runtime.h>
#include <cuda_fp16.h>

#define N_NODES 100000
#define N_EDGES 1600000
#define COUT 64
#define CIN 128
#define NBLK_SCAN 391   // ceil(100000/256)

// ---------------- scratch (no allocations allowed) ----------------
// Zero at module load; k_fold re-zeros what must be zero before the next
// replay, so every graph replay sees identical initial state.
__device__ int    g_degi[N_NODES];               // edge in-degree (no self loop)
__device__ float  g_dinv[N_NODES];
__device__ __half g_xsh[(size_t)N_NODES * COUT]; // (x@W)*dinv[row], fp16 payload
__device__ int    g_off[N_NODES];                // CSR offsets (global)
__device__ int    g_cnt[N_NODES];                // cursor: init=off, bin advances
__device__ int    g_srow[N_EDGES];               // CSR-sorted source row ids
__device__ int    g_bsum[512];
__device__ int    g_flag[512];
__device__ float  g_sums[COUT];
__device__ float  g_sumsq[COUT];
__device__ float  g_A[COUT];
__device__ float  g_B[COUT];

// packed f32x2 helpers
__device__ __forceinline__ unsigned long long pack_dup(float x) {
    unsigned long long p;
    unsigned u = __float_as_uint(x);
    asm("mov.b64 %0, {%1, %1};" : "=l"(p) : "r"(u));
    return p;
}
__device__ __forceinline__ void ffma2(unsigned long long& d,
                                      unsigned long long a,
                                      unsigned long long b) {
    asm("fma.rn.f32x2 %0, %1, %2, %3;" : "=l"(d) : "l"(a), "l"(b), "l"(d));
}
__device__ __forceinline__ void unpack2(unsigned long long p, float& lo, float& hi) {
    unsigned a, b2;
    asm("mov.b64 {%0, %1}, %2;" : "=r"(a), "=r"(b2) : "l"(p));
    lo = __uint_as_float(a);
    hi = __uint_as_float(b2);
}
__device__ __forceinline__ unsigned h2raw(float a, float b) {
    __half2 h = __floats2half2_rn(a, b);
    return *reinterpret_cast<unsigned*>(&h);
}

// ---------------- 1. degree count: 4 edges/thread via int4 ----------------
__global__ void k_deg(const int* __restrict__ col) {
    int t = blockIdx.x * blockDim.x + threadIdx.x;
    if (t < N_EDGES / 4) {
        int4 c = ((const int4*)col)[t];
        atomicAdd(&g_degi[c.x], 1);
        atomicAdd(&g_degi[c.y], 1);
        atomicAdd(&g_degi[c.z], 1);
        atomicAdd(&g_degi[c.w], 1);
    }
}

// ---------------- 2. single-pass scan: dinv + offsets + bin cursor -----------
// 391 blocks co-resident in one wave; lookback spin cannot deadlock.
__global__ void __launch_bounds__(256) k_scan1() {
    __shared__ int s[256];
    __shared__ int r2[256];
    const int tid = threadIdx.x;
    const int bid = blockIdx.x;
    const int i = bid * 256 + tid;
    int v = 0;
    if (i < N_NODES) {
        v = g_degi[i];
        g_dinv[i] = rsqrtf((float)v + 1.0f);   // deg incl self loop
    }
    s[tid] = v;
    __syncthreads();
    #pragma unroll
    for (int d = 1; d < 256; d <<= 1) {
        int t = (tid >= d) ? s[tid - d] : 0;
        __syncthreads();
        s[tid] += t;
        __syncthreads();
    }
    if (tid == 255) {
        atomicExch(&g_bsum[bid], s[255]);
        __threadfence();
        atomicExch(&g_flag[bid], 1);
    }
    int p = 0;
    for (int k = tid; k < bid; k += 256) {
        while (atomicAdd(&g_flag[k], 0) == 0) { }
        p += atomicAdd(&g_bsum[k], 0);
    }
    r2[tid] = p;
    __syncthreads();
    #pragma unroll
    for (int d = 128; d > 0; d >>= 1) {
        if (tid < d) r2[tid] += r2[tid + d];
        __syncthreads();
    }
    if (i < N_NODES) {
        int off = r2[0] + s[tid] - v;
        g_off[i] = off;
        g_cnt[i] = off;          // bin cursor starts at the CSR offset
    }
}

// ---------------- 3. bin: cursor atomic gives absolute position --------------
__global__ void k_bin(const int* __restrict__ rowIdx, const int* __restrict__ colIdx) {
    int t = blockIdx.x * blockDim.x + threadIdx.x;
    if (t < N_EDGES / 4) {
        int4 r = ((const int4*)rowIdx)[t];
        int4 c = ((const int4*)colIdx)[t];
        int p0 = atomicAdd(&g_cnt[c.x], 1);
        int p1 = atomicAdd(&g_cnt[c.y], 1);
        int p2 = atomicAdd(&g_cnt[c.z], 1);
        int p3 = atomicAdd(&g_cnt[c.w], 1);
        g_srow[p0] = r.x;
        g_srow[p1] = r.y;
        g_srow[p2] = r.z;
        g_srow[p3] = r.w;
    }
}

// ---------------- 4. GEMM: xsh = half((x @ W) * dinv[row]) -------------------
// 128-row x 64-col tile, 256 threads, 4x8 per thread (acc = 32 regs),
// 3 CTAs/SM target for latency hiding.
#define XPAD 132
__global__ void __launch_bounds__(256, 3) k_gemm(const float* __restrict__ x,
                                                 const float* __restrict__ W) {
    extern __shared__ float smem[];
    float* sW = smem;              // 8192 floats (32KB)
    float* sX = smem + 8192;       // 32 * 132 floats
    const int tid = threadIdx.x;
    const int base = blockIdx.x * 128;

    {
        const float4* W4 = (const float4*)W;
        float4* sW4 = (float4*)sW;
        #pragma unroll
        for (int i = tid; i < 2048; i += 256) sW4[i] = W4[i];
    }

    const int c0 = (tid & 7) * 8;    // 8 output cols (4 packed pairs)
    const int r0 = (tid >> 3) * 4;   // 4 output rows

    unsigned long long acc[4][4];
    #pragma unroll
    for (int j = 0; j < 4; j++)
        #pragma unroll
        for (int p = 0; p < 4; p++) acc[j][p] = 0ULL;

    const float4* x4 = (const float4*)x;

    for (int cc = 0; cc < 4; cc++) {
        const int k0 = cc * 32;
        __syncthreads();
        // stage x[base..base+127][k0..k0+31] transposed into sX[k][r]
        #pragma unroll
        for (int t = 0; t < 4; t++) {
            int idx = tid + t * 256;          // 0..1023
            int r = idx >> 3;                 // 0..127
            int kq = idx & 7;                 // float4 within 32-k chunk
            int row = base + r;
            float4 v = make_float4(0.f, 0.f, 0.f, 0.f);
            if (row < N_NODES) v = x4[row * 32 + (k0 >> 2) + kq];
            int kl = kq << 2;
            sX[(kl + 0) * XPAD + r] = v.x;
            sX[(kl + 1) * XPAD + r] = v.y;
            sX[(kl + 2) * XPAD + r] = v.z;
            sX[(kl + 3) * XPAD + r] = v.w;
        }
        __syncthreads();

        #pragma unroll 4
        for (int kk = 0; kk < 32; kk++) {
            const int k = k0 + kk;
            ulonglong2 wp0 = *(const ulonglong2*)&sW[k * 64 + c0];
            ulonglong2 wp1 = *(const ulonglong2*)&sW[k * 64 + c0 + 4];
            unsigned long long wv[4] = {wp0.x, wp0.y, wp1.x, wp1.y};
            float4 xv = *(const float4*)&sX[kk * XPAD + r0];
            float xr[4] = {xv.x, xv.y, xv.z, xv.w};
            #pragma unroll
            for (int j = 0; j < 4; j++) {
                unsigned long long xd = pack_dup(xr[j]);
                #pragma unroll
                for (int p = 0; p < 4; p++) ffma2(acc[j][p], xd, wv[p]);
            }
        }
    }

    // epilogue: scale by dinv[row], convert to fp16, single 16B store per row
    #pragma unroll
    for (int j = 0; j < 4; j++) {
        int row = base + r0 + j;
        if (row < N_NODES) {
            float di = g_dinv[row];
            float o[8];
            #pragma unroll
            for (int p = 0; p < 4; p++) unpack2(acc[j][p], o[2 * p], o[2 * p + 1]);
            uint4 hv = make_uint4(h2raw(o[0] * di, o[1] * di),
                                  h2raw(o[2] * di, o[3] * di),
                                  h2raw(o[4] * di, o[5] * di),
                                  h2raw(o[6] * di, o[7] * di));
            *(uint4*)&g_xsh[(size_t)row * 64 + c0] = hv;
        }
    }
}

// ---------------- 5. CSR gather-aggregate (fp16 payload) + fused BN stats ----
// 16 lanes per node; lane loads 8B (4 halves) per edge, broadcast index loads.
__global__ void __launch_bounds__(256) k_agg(float* __restrict__ out,
                                             const float* __restrict__ b) {
    __shared__ float s1[COUT], s2m[COUT];
    const int tid = threadIdx.x;
    if (tid < COUT) { s1[tid] = 0.f; s2m[tid] = 0.f; }
    __syncthreads();

    const int gid = blockIdx.x * 256 + tid;
    const int comp = tid & 15;
    float sum0 = 0.f, sum1 = 0.f, sum2 = 0.f, sum3 = 0.f;
    float sq0 = 0.f, sq1 = 0.f, sq2 = 0.f, sq3 = 0.f;

    if (gid < N_NODES * 16) {
        const int node = gid >> 4;
        const uint2* xsh = (const uint2*)g_xsh;   // 16 uint2 per row

        // self loop term (fp16 payload)
        uint2 us = xsh[gid];
        float2 s0 = __half22float2(*(__half2*)&us.x);
        float2 sl1 = __half22float2(*(__half2*)&us.y);
        float4 acc = make_float4(s0.x, s0.y, sl1.x, sl1.y);

        const int beg = g_off[node];
        const int end = beg + g_degi[node];
        int j = beg;
        for (; j + 4 <= end; j += 4) {
            int r0 = g_srow[j], r1 = g_srow[j + 1];
            int r2 = g_srow[j + 2], r3 = g_srow[j + 3];
            uint2 ua = xsh[r0 * 16 + comp];
            uint2 ub = xsh[r1 * 16 + comp];
            uint2 uc = xsh[r2 * 16 + comp];
            uint2 ud = xsh[r3 * 16 + comp];
            float2 a0 = __half22float2(*(__half2*)&ua.x);
            float2 a1 = __half22float2(*(__half2*)&ua.y);
            float2 b0 = __half22float2(*(__half2*)&ub.x);
            float2 b1 = __half22float2(*(__half2*)&ub.y);
            float2 c0 = __half22float2(*(__half2*)&uc.x);
            float2 c1 = __half22float2(*(__half2*)&uc.y);
            float2 d0 = __half22float2(*(__half2*)&ud.x);
            float2 d1 = __half22float2(*(__half2*)&ud.y);
            acc.x += (a0.x + b0.x) + (c0.x + d0.x);
            acc.y += (a0.y + b0.y) + (c0.y + d0.y);
            acc.z += (a1.x + b1.x) + (c1.x + d1.x);
            acc.w += (a1.y + b1.y) + (c1.y + d1.y);
        }
        for (; j < end; j++) {
            uint2 ua = xsh[g_srow[j] * 16 + comp];
            float2 a0 = __half22float2(*(__half2*)&ua.x);
            float2 a1 = __half22float2(*(__half2*)&ua.y);
            acc.x += a0.x; acc.y += a0.y; acc.z += a1.x; acc.w += a1.y;
        }
        const float di = g_dinv[node];
        acc.x *= di; acc.y *= di; acc.z *= di; acc.w *= di;
        ((float4*)out)[gid] = acc;

        const float4 bv = ((const float4*)b)[comp];
        float o0 = acc.x + bv.x, o1 = acc.y + bv.y;
        float o2 = acc.z + bv.z, o3 = acc.w + bv.w;
        sum0 = o0; sq0 = o0 * o0;
        sum1 = o1; sq1 = o1 * o1;
        sum2 = o2; sq2 = o2 * o2;
        sum3 = o3; sq3 = o3 * o3;
    }

    const int cb = comp * 4;
    atomicAdd(&s1[cb + 0], sum0); atomicAdd(&s2m[cb + 0], sq0);
    atomicAdd(&s1[cb + 1], sum1); atomicAdd(&s2m[cb + 1], sq1);
    atomicAdd(&s1[cb + 2], sum2); atomicAdd(&s2m[cb + 2], sq2);
    atomicAdd(&s1[cb + 3], sum3); atomicAdd(&s2m[cb + 3], sq3);
    __syncthreads();
    if (tid < COUT) {
        atomicAdd(&g_sums[tid], s1[tid]);
        atomicAdd(&g_sumsq[tid], s2m[tid]);
    }
}

// ---------------- 6. fold BN + re-zero scratch for next replay ---------------
__global__ void __launch_bounds__(256) k_fold(const float* __restrict__ b,
                                              const float* __restrict__ gamma,
                                              const float* __restrict__ beta) {
    const int bid = blockIdx.x;
    const int tid = threadIdx.x;
    if (bid == 0 && tid < COUT) {
        float inv_n = 1.0f / (float)N_NODES;
        float mean = g_sums[tid] * inv_n;
        float var = g_sumsq[tid] * inv_n - mean * mean;
        float scale = gamma[tid] * rsqrtf(var + 1e-5f);
        g_A[tid] = scale;
        g_B[tid] = scale * (b[tid] - mean) + beta[tid];
        g_sums[tid] = 0.f;
        g_sumsq[tid] = 0.f;
    }
    const int i = bid * 256 + tid;
    if (i < N_NODES) g_degi[i] = 0;
    if (i < 512) { g_flag[i] = 0; g_bsum[i] = 0; }
}

// ---------------- 7. final: y = leaky(A*v + B), in place ----------------
__global__ void __launch_bounds__(256) k_final(float* __restrict__ out) {
    int q = blockIdx.x * 256 + threadIdx.x;
    if (q >= N_NODES * 16) return;
    int cq = q & 15;
    float4 a = ((const float4*)g_A)[cq];
    float4 bb = ((const float4*)g_B)[cq];
    float4 v = ((float4*)out)[q];
    float4 y;
    y.x = a.x * v.x + bb.x;
    y.y = a.y * v.y + bb.y;
    y.z = a.z * v.z + bb.z;
    y.w = a.w * v.w + bb.w;
    y.x = (y.x >= 0.f) ? y.x : 0.01f * y.x;
    y.y = (y.y >= 0.f) ? y.y : 0.01f * y.y;
    y.z = (y.z >= 0.f) ? y.z : 0.01f * y.z;
    y.w = (y.w >= 0.f) ? y.w : 0.01f * y.w;
    ((float4*)out)[q] = y;
}

extern "C" void kernel_launch(void* const* d_in, const int* in_sizes, int n_in,
                              void* d_out, int out_size) {
    const float* x      = (const float*)d_in[0];
    const int*   eidx   = (const int*)d_in[1];     // [2, E]: row then col
    const float* W      = (const float*)d_in[2];
    const float* b      = (const float*)d_in[3];
    const float* gamma  = (const float*)d_in[4];
    const float* beta   = (const float*)d_in[5];
    float* out = (float*)d_out;

    const int* rowIdx = eidx;
    const int* colIdx = eidx + N_EDGES;

    static bool init_done = false;
    const int gemm_smem = (8192 + 32 * XPAD) * sizeof(float);   // 49664 B
    if (!init_done) {
        cudaFuncSetAttribute(k_gemm, cudaFuncAttributeMaxDynamicSharedMemorySize, gemm_smem);
        init_done = true;
    }

    k_deg<<<(N_EDGES / 4 + 255) / 256, 256>>>(colIdx);
    k_scan1<<<NBLK_SCAN, 256>>>();
    k_bin<<<(N_EDGES / 4 + 255) / 256, 256>>>(rowIdx, colIdx);
    k_gemm<<<(N_NODES + 127) / 128, 256, gemm_smem>>>(x, W);
    k_agg<<<(N_NODES * 16 + 255) / 256, 256>>>(out, b);
    k_fold<<<NBLK_SCAN, 256>>>(b, gamma, beta);
    k_final<<<(N_NODES * 16 + 255) / 256, 256>>>(out);
}

// round 10
// speedup vs baseline: 1.3213x; 1.3213x over previous
#include <cuda_runtime.h>
#include <cuda_fp16.h>

#define N_NODES 100000
#define N_EDGES 1600000
#define COUT 64
#define CIN 128
#define NBLK_SCAN 391   // ceil(100000/256)

// ---------------- scratch (no allocations allowed) ----------------
__device__ int    g_degi[N_NODES];               // edge in-degree (no self loop)
__device__ float  g_dinv[N_NODES];
__device__ __half g_xsh[(size_t)N_NODES * COUT]; // (x@W)*dinv[row], fp16 payload
__device__ int    g_off[N_NODES];                // CSR offsets (global)
__device__ int    g_cnt[N_NODES];                // cursor: init=off, bin advances
__device__ int    g_srow[N_EDGES];               // CSR-sorted source row ids
__device__ int    g_bsum[512];
__device__ int    g_flag[512];
__device__ float  g_sums[COUT];
__device__ float  g_sumsq[COUT];
__device__ float  g_A[COUT];
__device__ float  g_B[COUT];

// ---------------- 1. degree count: 4 edges/thread via int4 ----------------
__global__ void k_deg(const int* __restrict__ col) {
    int t = blockIdx.x * blockDim.x + threadIdx.x;
    if (t < N_EDGES / 4) {
        int4 c = ((const int4*)col)[t];
        atomicAdd(&g_degi[c.x], 1);
        atomicAdd(&g_degi[c.y], 1);
        atomicAdd(&g_degi[c.z], 1);
        atomicAdd(&g_degi[c.w], 1);
    }
}

// ---------------- 2. single-pass scan: dinv + offsets + bin cursor -----------
__global__ void __launch_bounds__(256) k_scan1() {
    __shared__ int s[256];
    __shared__ int r2[256];
    const int tid = threadIdx.x;
    const int bid = blockIdx.x;
    const int i = bid * 256 + tid;
    int v = 0;
    if (i < N_NODES) {
        v = g_degi[i];
        g_dinv[i] = rsqrtf((float)v + 1.0f);   // deg incl self loop
    }
    s[tid] = v;
    __syncthreads();
    #pragma unroll
    for (int d = 1; d < 256; d <<= 1) {
        int t = (tid >= d) ? s[tid - d] : 0;
        __syncthreads();
        s[tid] += t;
        __syncthreads();
    }
    if (tid == 255) {
        atomicExch(&g_bsum[bid], s[255]);
        __threadfence();
        atomicExch(&g_flag[bid], 1);
    }
    int p = 0;
    for (int k = tid; k < bid; k += 256) {
        while (atomicAdd(&g_flag[k], 0) == 0) { }
        p += atomicAdd(&g_bsum[k], 0);
    }
    r2[tid] = p;
    __syncthreads();
    #pragma unroll
    for (int d = 128; d > 0; d >>= 1) {
        if (tid < d) r2[tid] += r2[tid + d];
        __syncthreads();
    }
    if (i < N_NODES) {
        int off = r2[0] + s[tid] - v;
        g_off[i] = off;
        g_cnt[i] = off;          // bin cursor starts at the CSR offset
    }
}

// ---------------- 3. bin: cursor atomic gives absolute position --------------
__global__ void k_bin(const int* __restrict__ rowIdx, const int* __restrict__ colIdx) {
    int t = blockIdx.x * blockDim.x + threadIdx.x;
    if (t < N_EDGES / 4) {
        int4 r = ((const int4*)rowIdx)[t];
        int4 c = ((const int4*)colIdx)[t];
        int p0 = atomicAdd(&g_cnt[c.x], 1);
        int p1 = atomicAdd(&g_cnt[c.y], 1);
        int p2 = atomicAdd(&g_cnt[c.z], 1);
        int p3 = atomicAdd(&g_cnt[c.w], 1);
        g_srow[p0] = r.x;
        g_srow[p1] = r.y;
        g_srow[p2] = r.z;
        g_srow[p3] = r.w;
    }
}

// ---------------- 4. Tensor-core GEMM: xsh = half((x@W) * dinv[row]) ---------
// Split-fp16: x = xh + xl, W = wh + wl; acc = xh*wh + xh*wl + xl*wh in fp32.
// 64-row tile, 128 threads = 4 warps x 16 rows. Whole K=128 in smem.
// smem (halves): xh[64][136], xl[64][136], wh[128][72], wl[128][72]
#define SX_STR 136
#define SW_STR 72
#define SX_HI 0
#define SX_LO 8704
#define SW_HI 17408
#define SW_LO 26624
#define GEMM_SMEM_BYTES ((26624 + 9216) * 2)   // 71680

__device__ __forceinline__ void ldm_x4(unsigned& r0, unsigned& r1,
                                       unsigned& r2, unsigned& r3, unsigned a) {
    asm volatile("ldmatrix.sync.aligned.m8n8.x4.shared.b16 {%0,%1,%2,%3},[%4];"
                 : "=r"(r0), "=r"(r1), "=r"(r2), "=r"(r3) : "r"(a));
}
__device__ __forceinline__ void ldm_x2t(unsigned& r0, unsigned& r1, unsigned a) {
    asm volatile("ldmatrix.sync.aligned.m8n8.x2.trans.shared.b16 {%0,%1},[%2];"
                 : "=r"(r0), "=r"(r1) : "r"(a));
}
__device__ __forceinline__ void mma16816(float* c, const unsigned* a,
                                         const unsigned* b) {
    asm volatile("mma.sync.aligned.m16n8k16.row.col.f32.f16.f16.f32 "
                 "{%0,%1,%2,%3},{%4,%5,%6,%7},{%8,%9},{%0,%1,%2,%3};"
                 : "+f"(c[0]), "+f"(c[1]), "+f"(c[2]), "+f"(c[3])
                 : "r"(a[0]), "r"(a[1]), "r"(a[2]), "r"(a[3]),
                   "r"(b[0]), "r"(b[1]));
}
__device__ __forceinline__ void split16(float v, __half& h, __half& l) {
    h = __float2half_rn(v);
    l = __float2half_rn(v - __half2float(h));
}

__global__ void __launch_bounds__(128, 2) k_gemm(const float* __restrict__ x,
                                                 const float* __restrict__ W) {
    extern __shared__ __half sh[];
    const int tid = threadIdx.x;
    const int lane = tid & 31;
    const int warp = tid >> 5;
    const int base = blockIdx.x * 64;

    // ---- stage W (128x64) hi/lo: 2048 float4 / 128 threads = 16 iters ----
    {
        const float4* W4 = (const float4*)W;
        #pragma unroll
        for (int t = 0; t < 16; t++) {
            int idx = tid + t * 128;          // 0..2047
            int k = idx >> 4;                 // row (0..127)
            int q = idx & 15;                 // float4 within row
            float4 v = W4[idx];
            __half h0, l0, h1, l1, h2, l2, h3, l3;
            split16(v.x, h0, l0); split16(v.y, h1, l1);
            split16(v.z, h2, l2); split16(v.w, h3, l3);
            __half2* dh = (__half2*)&sh[SW_HI + k * SW_STR + q * 4];
            __half2* dl = (__half2*)&sh[SW_LO + k * SW_STR + q * 4];
            dh[0] = __halves2half2(h0, h1); dh[1] = __halves2half2(h2, h3);
            dl[0] = __halves2half2(l0, l1); dl[1] = __halves2half2(l2, l3);
        }
    }
    // ---- stage x tile (64x128) hi/lo: 2048 float4 / 128 threads ----
    {
        const float4* x4 = (const float4*)x;
        #pragma unroll
        for (int t = 0; t < 16; t++) {
            int idx = tid + t * 128;          // 0..2047
            int r = idx >> 5;                 // row in tile (0..63)
            int q = idx & 31;                 // float4 within row
            int row = base + r;
            float4 v = make_float4(0.f, 0.f, 0.f, 0.f);
            if (row < N_NODES) v = x4[row * 32 + q];
            __half h0, l0, h1, l1, h2, l2, h3, l3;
            split16(v.x, h0, l0); split16(v.y, h1, l1);
            split16(v.z, h2, l2); split16(v.w, h3, l3);
            __half2* dh = (__half2*)&sh[SX_HI + r * SX_STR + q * 4];
            __half2* dl = (__half2*)&sh[SX_LO + r * SX_STR + q * 4];
            dh[0] = __halves2half2(h0, h1); dh[1] = __halves2half2(h2, h3);
            dl[0] = __halves2half2(l0, l1); dl[1] = __halves2half2(l2, l3);
        }
    }
    __syncthreads();

    // ---- MMA mainloop ----
    float c[8][4];
    #pragma unroll
    for (int j = 0; j < 8; j++)
        #pragma unroll
        for (int p = 0; p < 4; p++) c[j][p] = 0.f;

    const unsigned sbase = (unsigned)__cvta_generic_to_shared(sh);
    // A-fragment lane address components
    const int quad = lane >> 3;
    const int r8 = lane & 7;
    const int arow = warp * 16 + (quad & 1) * 8 + r8;
    const int acol = (quad >> 1) * 8;
    // B-fragment lane address components (x2: lanes 0-15 used, mask to 16)
    const int bl = lane & 15;
    const int bk = (bl & 7) + ((bl >> 3) & 1) * 8;

    #pragma unroll
    for (int kc = 0; kc < 8; kc++) {
        unsigned ah[4], al[4];
        unsigned aoff = (arow * SX_STR + kc * 16 + acol) * 2;
        ldm_x4(ah[0], ah[1], ah[2], ah[3], sbase + SX_HI * 2 + aoff);
        ldm_x4(al[0], al[1], al[2], al[3], sbase + SX_LO * 2 + aoff);
        #pragma unroll
        for (int j = 0; j < 8; j++) {
            unsigned bh[2], blr[2];
            unsigned boff = ((kc * 16 + bk) * SW_STR + j * 8) * 2;
            ldm_x2t(bh[0], bh[1], sbase + SW_HI * 2 + boff);
            ldm_x2t(blr[0], blr[1], sbase + SW_LO * 2 + boff);
            mma16816(c[j], ah, bh);
            mma16816(c[j], ah, blr);
            mma16816(c[j], al, bh);
        }
    }

    // ---- epilogue: scale by dinv, fp16 store ----
    const int m0 = base + warp * 16 + (lane >> 2);
    const int m1 = m0 + 8;
    const int n0 = (lane & 3) * 2;
    float d0 = (m0 < N_NODES) ? g_dinv[m0] : 0.f;
    float d1 = (m1 < N_NODES) ? g_dinv[m1] : 0.f;
    #pragma unroll
    for (int j = 0; j < 8; j++) {
        if (m0 < N_NODES)
            *(__half2*)&g_xsh[(size_t)m0 * 64 + j * 8 + n0] =
                __floats2half2_rn(c[j][0] * d0, c[j][1] * d0);
        if (m1 < N_NODES)
            *(__half2*)&g_xsh[(size_t)m1 * 64 + j * 8 + n0] =
                __floats2half2_rn(c[j][2] * d1, c[j][3] * d1);
    }
}

// ---------------- 5. CSR gather-aggregate (fp16 payload) + fused BN stats ----
__global__ void __launch_bounds__(256) k_agg(float* __restrict__ out,
                                             const float* __restrict__ b) {
    __shared__ float s1[COUT], s2m[COUT];
    const int tid = threadIdx.x;
    if (tid < COUT) { s1[tid] = 0.f; s2m[tid] = 0.f; }
    __syncthreads();

    const int gid = blockIdx.x * 256 + tid;
    const int comp = tid & 15;
    float sum0 = 0.f, sum1 = 0.f, sum2 = 0.f, sum3 = 0.f;
    float sq0 = 0.f, sq1 = 0.f, sq2 = 0.f, sq3 = 0.f;

    if (gid < N_NODES * 16) {
        const int node = gid >> 4;
        const uint2* xsh = (const uint2*)g_xsh;   // 16 uint2 per row

        uint2 us = xsh[gid];
        float2 s0 = __half22float2(*(__half2*)&us.x);
        float2 sl1 = __half22float2(*(__half2*)&us.y);
        float4 acc = make_float4(s0.x, s0.y, sl1.x, sl1.y);

        const int beg = g_off[node];
        const int end = beg + g_degi[node];
        int j = beg;
        for (; j + 4 <= end; j += 4) {
            int r0 = g_srow[j], r1 = g_srow[j + 1];
            int r2 = g_srow[j + 2], r3 = g_srow[j + 3];
            uint2 ua = xsh[r0 * 16 + comp];
            uint2 ub = xsh[r1 * 16 + comp];
            uint2 uc = xsh[r2 * 16 + comp];
            uint2 ud = xsh[r3 * 16 + comp];
            float2 a0 = __half22float2(*(__half2*)&ua.x);
            float2 a1 = __half22float2(*(__half2*)&ua.y);
            float2 b0 = __half22float2(*(__half2*)&ub.x);
            float2 b1 = __half22float2(*(__half2*)&ub.y);
            float2 c0 = __half22float2(*(__half2*)&uc.x);
            float2 c1 = __half22float2(*(__half2*)&uc.y);
            float2 d0 = __half22float2(*(__half2*)&ud.x);
            float2 d1 = __half22float2(*(__half2*)&ud.y);
            acc.x += (a0.x + b0.x) + (c0.x + d0.x);
            acc.y += (a0.y + b0.y) + (c0.y + d0.y);
            acc.z += (a1.x + b1.x) + (c1.x + d1.x);
            acc.w += (a1.y + b1.y) + (c1.y + d1.y);
        }
        for (; j < end; j++) {
            uint2 ua = xsh[g_srow[j] * 16 + comp];
            float2 a0 = __half22float2(*(__half2*)&ua.x);
            float2 a1 = __half22float2(*(__half2*)&ua.y);
            acc.x += a0.x; acc.y += a0.y; acc.z += a1.x; acc.w += a1.y;
        }
        const float di = g_dinv[node];
        acc.x *= di; acc.y *= di; acc.z *= di; acc.w *= di;
        ((float4*)out)[gid] = acc;

        const float4 bv = ((const float4*)b)[comp];
        float o0 = acc.x + bv.x, o1 = acc.y + bv.y;
        float o2 = acc.z + bv.z, o3 = acc.w + bv.w;
        sum0 = o0; sq0 = o0 * o0;
        sum1 = o1; sq1 = o1 * o1;
        sum2 = o2; sq2 = o2 * o2;
        sum3 = o3; sq3 = o3 * o3;
    }

    const int cb = comp * 4;
    atomicAdd(&s1[cb + 0], sum0); atomicAdd(&s2m[cb + 0], sq0);
    atomicAdd(&s1[cb + 1], sum1); atomicAdd(&s2m[cb + 1], sq1);
    atomicAdd(&s1[cb + 2], sum2); atomicAdd(&s2m[cb + 2], sq2);
    atomicAdd(&s1[cb + 3], sum3); atomicAdd(&s2m[cb + 3], sq3);
    __syncthreads();
    if (tid < COUT) {
        atomicAdd(&g_sums[tid], s1[tid]);
        atomicAdd(&g_sumsq[tid], s2m[tid]);
    }
}

// ---------------- 6. fold BN + re-zero scratch for next replay ---------------
__global__ void __launch_bounds__(256) k_fold(const float* __restrict__ b,
                                              const float* __restrict__ gamma,
                                              const float* __restrict__ beta) {
    const int bid = blockIdx.x;
    const int tid = threadIdx.x;
    if (bid == 0 && tid < COUT) {
        float inv_n = 1.0f / (float)N_NODES;
        float mean = g_sums[tid] * inv_n;
        float var = g_sumsq[tid] * inv_n - mean * mean;
        float scale = gamma[tid] * rsqrtf(var + 1e-5f);
        g_A[tid] = scale;
        g_B[tid] = scale * (b[tid] - mean) + beta[tid];
        g_sums[tid] = 0.f;
        g_sumsq[tid] = 0.f;
    }
    const int i = bid * 256 + tid;
    if (i < N_NODES) g_degi[i] = 0;
    if (i < 512) { g_flag[i] = 0; g_bsum[i] = 0; }
}

// ---------------- 7. final: y = leaky(A*v + B), in place ----------------
__global__ void __launch_bounds__(256) k_final(float* __restrict__ out) {
    int q = blockIdx.x * 256 + threadIdx.x;
    if (q >= N_NODES * 16) return;
    int cq = q & 15;
    float4 a = ((const float4*)g_A)[cq];
    float4 bb = ((const float4*)g_B)[cq];
    float4 v = ((float4*)out)[q];
    float4 y;
    y.x = a.x * v.x + bb.x;
    y.y = a.y * v.y + bb.y;
    y.z = a.z * v.z + bb.z;
    y.w = a.w * v.w + bb.w;
    y.x = (y.x >= 0.f) ? y.x : 0.01f * y.x;
    y.y = (y.y >= 0.f) ? y.y : 0.01f * y.y;
    y.z = (y.z >= 0.f) ? y.z : 0.01f * y.z;
    y.w = (y.w >= 0.f) ? y.w : 0.01f * y.w;
    ((float4*)out)[q] = y;
}

extern "C" void kernel_launch(void* const* d_in, const int* in_sizes, int n_in,
                              void* d_out, int out_size) {
    const float* x      = (const float*)d_in[0];
    const int*   eidx   = (const int*)d_in[1];     // [2, E]: row then col
    const float* W      = (const float*)d_in[2];
    const float* b      = (const float*)d_in[3];
    const float* gamma  = (const float*)d_in[4];
    const float* beta   = (const float*)d_in[5];
    float* out = (float*)d_out;

    const int* rowIdx = eidx;
    const int* colIdx = eidx + N_EDGES;

    static bool init_done = false;
    if (!init_done) {
        cudaFuncSetAttribute(k_gemm, cudaFuncAttributeMaxDynamicSharedMemorySize,
                             GEMM_SMEM_BYTES);
        init_done = true;
    }

    k_deg<<<(N_EDGES / 4 + 255) / 256, 256>>>(colIdx);
    k_scan1<<<NBLK_SCAN, 256>>>();
    k_bin<<<(N_EDGES / 4 + 255) / 256, 256>>>(rowIdx, colIdx);
    k_gemm<<<(N_NODES + 63) / 64, 128, GEMM_SMEM_BYTES>>>(x, W);
    k_agg<<<(N_NODES * 16 + 255) / 256, 256>>>(out, b);
    k_fold<<<NBLK_SCAN, 256>>>(b, gamma, beta);
    k_final<<<(N_NODES * 16 + 255) / 256, 256>>>(out);
}